// round 3
// baseline (speedup 1.0000x reference)
#include <cuda_runtime.h>

#define NN 50000
#define NE 800000
#define NET (NN + NE)

// ---------------- scratch (no allocs allowed) ----------------
__device__ int    d_deg[NN];
__device__ int    d_rowptr[NN + 1];
__device__ int    d_next[NN];
__device__ int    d_csr_src[NET];
__device__ float  d_csr_ea[NET];
__device__ double d_attr_sum;

__device__ __align__(16) float d_xl1[NN * 128];
__device__ __align__(16) float d_xr1[NN * 128];
__device__ __align__(16) float d_h1 [NN * 128];
__device__ __align__(16) float d_xl2[NN * 64];
__device__ __align__(16) float d_xr2[NN * 64];

// ---------------- CSR build ----------------
__global__ void k_init() {
    int i = blockIdx.x * blockDim.x + threadIdx.x;
    if (i < NN) d_deg[i] = 1;           // reserve slot 0 of each node for its self-loop
    if (i == 0) d_attr_sum = 0.0;
}

__global__ void k_count(const int* __restrict__ ei, const float* __restrict__ eattr) {
    int e = blockIdx.x * blockDim.x + threadIdx.x;
    float v = 0.f;
    if (e < NE) {
        atomicAdd(&d_deg[ei[NE + e]], 1);
        v = eattr[e];
    }
    // block-reduce edge_attr for the self-loop mean
    for (int o = 16; o; o >>= 1) v += __shfl_xor_sync(0xffffffffu, v, o);
    __shared__ float ws[8];
    int lane = threadIdx.x & 31, wid = threadIdx.x >> 5;
    if (lane == 0) ws[wid] = v;
    __syncthreads();
    if (threadIdx.x == 0) {
        float s = 0.f;
        for (int w = 0; w < (int)(blockDim.x >> 5); w++) s += ws[w];
        atomicAdd(&d_attr_sum, (double)s);
    }
}

// single-block exclusive scan of degrees -> rowptr; also place self-loop in slot 0
__global__ void k_scan() {
    __shared__ int wsum[32];
    __shared__ int s_carry;
    int t = threadIdx.x, lane = t & 31, wid = t >> 5;
    if (t == 0) s_carry = 0;
    __syncthreads();
    float mean = (float)(d_attr_sum / (double)NE);
    for (int base = 0; base < NN; base += 1024) {
        int n = base + t;
        int orig = (n < NN) ? d_deg[n] : 0;
        int v = orig;
        for (int o = 1; o < 32; o <<= 1) {
            int y = __shfl_up_sync(0xffffffffu, v, o);
            if (lane >= o) v += y;
        }
        if (lane == 31) wsum[wid] = v;
        __syncthreads();
        if (wid == 0) {
            int w = wsum[lane];
            for (int o = 1; o < 32; o <<= 1) {
                int y = __shfl_up_sync(0xffffffffu, w, o);
                if (lane >= o) w += y;
            }
            wsum[lane] = w;
        }
        __syncthreads();
        int start = s_carry + v + (wid ? wsum[wid - 1] : 0) - orig;
        int total = wsum[31];
        if (n < NN) {
            d_rowptr[n]  = start;
            d_next[n]    = start + 1;
            d_csr_src[start] = n;       // self-loop src
            d_csr_ea [start] = mean;    // self-loop edge attr = mean(edge_attr)
        }
        __syncthreads();
        if (t == 0) s_carry += total;
        __syncthreads();
    }
    if (t == 0) d_rowptr[NN] = s_carry;
}

__global__ void k_fill(const int* __restrict__ ei, const float* __restrict__ eattr) {
    int e = blockIdx.x * blockDim.x + threadIdx.x;
    if (e >= NE) return;
    int src = ei[e], dst = ei[NE + e];
    int slot = atomicAdd(&d_next[dst], 1);
    d_csr_src[slot] = src;
    d_csr_ea [slot] = eattr[e];
}

// ---------------- fp32 GEMM: O[rows,ncols] = A[rows,128] @ W[128,ncols] + bias ----------------
// block tile: 128 rows x 64 cols; thread tile 8x4; K = 128 fully resident in smem.
// Ash row stride = 132 floats (multiple of 4 -> float4-aligned; pad avoids worst conflicts).
#define ASTRIDE 132
__global__ void __launch_bounds__(256) k_gemm(const float* __restrict__ A,
                                              const float* __restrict__ W,
                                              const float* __restrict__ bias,
                                              float* __restrict__ O,
                                              int rows, int ncols) {
    extern __shared__ float sm[];
    float* Ash = sm;                   // 128 x ASTRIDE
    float* Wsh = sm + 128 * ASTRIDE;   // 128 x 64
    int t  = threadIdx.x;
    int rb = blockIdx.x * 128, cb = blockIdx.y * 64;

    const float4* A4 = (const float4*)A;
    for (int i = t; i < 128 * 32; i += 256) {
        int r = i >> 5, c4 = i & 31;
        int gr = rb + r;
        float4 v = (gr < rows) ? A4[gr * 32 + c4] : make_float4(0.f, 0.f, 0.f, 0.f);
        *(float4*)&Ash[r * ASTRIDE + c4 * 4] = v;
    }
    for (int i = t; i < 128 * 16; i += 256) {
        int k = i >> 4, c4 = i & 15;
        *(float4*)&Wsh[k * 64 + c4 * 4] = *(const float4*)&W[k * ncols + cb + c4 * 4];
    }
    __syncthreads();

    int tc = t & 15, tr = t >> 4;
    float acc[8][4];
#pragma unroll
    for (int r = 0; r < 8; r++)
#pragma unroll
        for (int c = 0; c < 4; c++) acc[r][c] = 0.f;

#pragma unroll 4
    for (int k = 0; k < 128; k++) {
        float4 wv = *(float4*)&Wsh[k * 64 + tc * 4];
#pragma unroll
        for (int r = 0; r < 8; r++) {
            float av = Ash[(tr * 8 + r) * ASTRIDE + k];
            acc[r][0] += av * wv.x;
            acc[r][1] += av * wv.y;
            acc[r][2] += av * wv.z;
            acc[r][3] += av * wv.w;
        }
    }

    float4 bv = *(const float4*)&bias[cb + tc * 4];
#pragma unroll
    for (int r = 0; r < 8; r++) {
        int row = rb + tr * 8 + r;
        if (row < rows) {
            float4 o = make_float4(acc[r][0] + bv.x, acc[r][1] + bv.y,
                                   acc[r][2] + bv.z, acc[r][3] + bv.w);
            *(float4*)&O[row * ncols + cb + tc * 4] = o;
        }
    }
}

// ---------------- GATv2 layer 1: heads=4, D=32, concat, ELU ----------------
// one warp per destination node; lane = feature dim within head.
__global__ void __launch_bounds__(256) k_gat1(const float* __restrict__ xl,
                                              const float* __restrict__ xr,
                                              const float* __restrict__ we,
                                              const float* __restrict__ att,
                                              const float* __restrict__ bias,
                                              float* __restrict__ out) {
    int w = (blockIdx.x * blockDim.x + threadIdx.x) >> 5;
    if (w >= NN) return;
    int lane = threadIdx.x & 31;
    int n = w;

    float xr_r[4], we_r[4], att_r[4];
#pragma unroll
    for (int h = 0; h < 4; h++) {
        int c = h * 32 + lane;
        xr_r[h]  = xr[n * 128 + c];
        we_r[h]  = __ldg(we + c);
        att_r[h] = __ldg(att + c);
    }
    int d0 = d_rowptr[n], d1 = d_rowptr[n + 1];

    // pass 1: segment max of scores
    float mx[4] = {-1e30f, -1e30f, -1e30f, -1e30f};
    for (int i = d0; i < d1; i++) {
        int s = d_csr_src[i];
        float eav = d_csr_ea[i];
#pragma unroll
        for (int h = 0; h < 4; h++) {
            float z = __ldg(xl + s * 128 + h * 32 + lane) + xr_r[h] + eav * we_r[h];
            z = fmaxf(z, 0.2f * z);                 // leaky_relu(0.2)
            float v = z * att_r[h];
            for (int o = 16; o; o >>= 1) v += __shfl_xor_sync(0xffffffffu, v, o);
            mx[h] = fmaxf(mx[h], v);
        }
    }
    // pass 2: exp-weighted aggregation (scores recomputed from same gathered xl)
    float den[4] = {0.f, 0.f, 0.f, 0.f}, acc[4] = {0.f, 0.f, 0.f, 0.f};
    for (int i = d0; i < d1; i++) {
        int s = d_csr_src[i];
        float eav = d_csr_ea[i];
#pragma unroll
        for (int h = 0; h < 4; h++) {
            float xlv = __ldg(xl + s * 128 + h * 32 + lane);
            float z = xlv + xr_r[h] + eav * we_r[h];
            z = fmaxf(z, 0.2f * z);
            float v = z * att_r[h];
            for (int o = 16; o; o >>= 1) v += __shfl_xor_sync(0xffffffffu, v, o);
            float ex = __expf(v - mx[h]);
            den[h] += ex;
            acc[h] += ex * xlv;
        }
    }
#pragma unroll
    for (int h = 0; h < 4; h++) {
        float o = acc[h] / den[h] + __ldg(bias + h * 32 + lane);
        out[n * 128 + h * 32 + lane] = (o > 0.f) ? o : expm1f(o);   // ELU
    }
}

// ---------------- GATv2 layer 2 (heads=2, mean) + ELU + classifier, fused ----------------
__global__ void __launch_bounds__(256) k_gat2(const float* __restrict__ xl,
                                              const float* __restrict__ xr,
                                              const float* __restrict__ we,
                                              const float* __restrict__ att,
                                              const float* __restrict__ bias,
                                              const float* __restrict__ wc,
                                              const float* __restrict__ bc,
                                              float* __restrict__ out) {
    int w = (blockIdx.x * blockDim.x + threadIdx.x) >> 5;
    if (w >= NN) return;
    int lane = threadIdx.x & 31;
    int n = w;

    float xr_r[2], we_r[2], att_r[2];
#pragma unroll
    for (int h = 0; h < 2; h++) {
        int c = h * 32 + lane;
        xr_r[h]  = xr[n * 64 + c];
        we_r[h]  = __ldg(we + c);
        att_r[h] = __ldg(att + c);
    }
    int d0 = d_rowptr[n], d1 = d_rowptr[n + 1];

    float mx[2] = {-1e30f, -1e30f};
    for (int i = d0; i < d1; i++) {
        int s = d_csr_src[i];
        float eav = d_csr_ea[i];
#pragma unroll
        for (int h = 0; h < 2; h++) {
            float z = __ldg(xl + s * 64 + h * 32 + lane) + xr_r[h] + eav * we_r[h];
            z = fmaxf(z, 0.2f * z);
            float v = z * att_r[h];
            for (int o = 16; o; o >>= 1) v += __shfl_xor_sync(0xffffffffu, v, o);
            mx[h] = fmaxf(mx[h], v);
        }
    }
    float den[2] = {0.f, 0.f}, acc[2] = {0.f, 0.f};
    for (int i = d0; i < d1; i++) {
        int s = d_csr_src[i];
        float eav = d_csr_ea[i];
#pragma unroll
        for (int h = 0; h < 2; h++) {
            float xlv = __ldg(xl + s * 64 + h * 32 + lane);
            float z = xlv + xr_r[h] + eav * we_r[h];
            z = fmaxf(z, 0.2f * z);
            float v = z * att_r[h];
            for (int o = 16; o; o >>= 1) v += __shfl_xor_sync(0xffffffffu, v, o);
            float ex = __expf(v - mx[h]);
            den[h] += ex;
            acc[h] += ex * xlv;
        }
    }
    // mean over heads + bias + ELU -> t[lane]
    float tv = 0.5f * (acc[0] / den[0] + acc[1] / den[1]) + __ldg(bias + lane);
    tv = (tv > 0.f) ? tv : expm1f(tv);

    // classifier: out[n][j] = sum_d t[d] * wc[d][j] + bc[j]   (wc: 32x8)
    float4 wA = __ldg((const float4*)wc + lane * 2);
    float4 wB = __ldg((const float4*)wc + lane * 2 + 1);
    float p0 = tv * wA.x, p1 = tv * wA.y, p2 = tv * wA.z, p3 = tv * wA.w;
    float p4 = tv * wB.x, p5 = tv * wB.y, p6 = tv * wB.z, p7 = tv * wB.w;
    for (int o = 16; o; o >>= 1) {
        p0 += __shfl_xor_sync(0xffffffffu, p0, o);
        p1 += __shfl_xor_sync(0xffffffffu, p1, o);
        p2 += __shfl_xor_sync(0xffffffffu, p2, o);
        p3 += __shfl_xor_sync(0xffffffffu, p3, o);
        p4 += __shfl_xor_sync(0xffffffffu, p4, o);
        p5 += __shfl_xor_sync(0xffffffffu, p5, o);
        p6 += __shfl_xor_sync(0xffffffffu, p6, o);
        p7 += __shfl_xor_sync(0xffffffffu, p7, o);
    }
    if (lane == 0) {
        float4 o0 = make_float4(p0 + __ldg(bc + 0), p1 + __ldg(bc + 1),
                                p2 + __ldg(bc + 2), p3 + __ldg(bc + 3));
        float4 o1 = make_float4(p4 + __ldg(bc + 4), p5 + __ldg(bc + 5),
                                p6 + __ldg(bc + 6), p7 + __ldg(bc + 7));
        *(float4*)&out[n * 8]     = o0;
        *(float4*)&out[n * 8 + 4] = o1;
    }
}

// ---------------- launch ----------------
extern "C" void kernel_launch(void* const* d_in, const int* in_sizes, int n_in,
                              void* d_out, int out_size) {
    const float* x     = (const float*)d_in[0];
    const int*   ei    = (const int*)  d_in[1];
    const float* eattr = (const float*)d_in[2];
    const float* w1l   = (const float*)d_in[3];
    const float* b1l   = (const float*)d_in[4];
    const float* w1r   = (const float*)d_in[5];
    const float* b1r   = (const float*)d_in[6];
    const float* w1e   = (const float*)d_in[7];
    const float* att1  = (const float*)d_in[8];
    const float* bias1 = (const float*)d_in[9];
    const float* w2l   = (const float*)d_in[10];
    const float* b2l   = (const float*)d_in[11];
    const float* w2r   = (const float*)d_in[12];
    const float* b2r   = (const float*)d_in[13];
    const float* w2e   = (const float*)d_in[14];
    const float* att2  = (const float*)d_in[15];
    const float* bias2 = (const float*)d_in[16];
    const float* wc    = (const float*)d_in[17];
    const float* bc    = (const float*)d_in[18];
    float* out = (float*)d_out;

    void *pxl1, *pxr1, *ph1, *pxl2, *pxr2;
    cudaGetSymbolAddress(&pxl1, d_xl1);
    cudaGetSymbolAddress(&pxr1, d_xr1);
    cudaGetSymbolAddress(&ph1,  d_h1);
    cudaGetSymbolAddress(&pxl2, d_xl2);
    cudaGetSymbolAddress(&pxr2, d_xr2);

    // CSR build (per launch; deterministic up to fp atomic ordering of the mean)
    k_init <<<(NN + 255) / 256, 256>>>();
    k_count<<<(NE + 255) / 256, 256>>>(ei, eattr);
    k_scan <<<1, 1024>>>();
    k_fill <<<(NE + 255) / 256, 256>>>(ei, eattr);

    size_t smem = (size_t)(128 * ASTRIDE + 128 * 64) * sizeof(float);
    cudaFuncSetAttribute(k_gemm, cudaFuncAttributeMaxDynamicSharedMemorySize, (int)smem);

    dim3 g1((NN + 127) / 128, 2);
    k_gemm<<<g1, 256, smem>>>(x, w1l, b1l, (float*)pxl1, NN, 128);
    k_gemm<<<g1, 256, smem>>>(x, w1r, b1r, (float*)pxr1, NN, 128);

    int gat_blocks = (NN * 32 + 255) / 256;
    k_gat1<<<gat_blocks, 256>>>((const float*)pxl1, (const float*)pxr1,
                                w1e, att1, bias1, (float*)ph1);

    dim3 g2((NN + 127) / 128, 1);
    k_gemm<<<g2, 256, smem>>>((const float*)ph1, w2l, b2l, (float*)pxl2, NN, 64);
    k_gemm<<<g2, 256, smem>>>((const float*)ph1, w2r, b2r, (float*)pxr2, NN, 64);

    k_gat2<<<gat_blocks, 256>>>((const float*)pxl2, (const float*)pxr2,
                                w2e, att2, bias2, wc, bc, out);
}

// round 4
// speedup vs baseline: 1.5670x; 1.5670x over previous
#include <cuda_runtime.h>

#define NN 50000
#define NE 800000
#define NET (NN + NE)

// ---------------- scratch (no allocs allowed) ----------------
__device__ int    d_deg[NN];
__device__ int    d_rowptr[NN + 1];
__device__ int    d_next[NN];
__device__ __align__(16) int2 d_csr[NET];      // {src, float_bits(edge_attr)}
__device__ double d_attr_sum;

__device__ __align__(16) float d_xl1[NN * 128];
__device__ __align__(16) float d_xr1[NN * 128];
__device__ __align__(16) float d_h1 [NN * 128];
__device__ __align__(16) float d_xl2[NN * 64];
__device__ __align__(16) float d_xr2[NN * 64];

// ---------------- CSR build ----------------
__global__ void k_init() {
    int i = blockIdx.x * blockDim.x + threadIdx.x;
    if (i < NN) d_deg[i] = 1;           // slot 0 of each node = its self-loop
    if (i == 0) d_attr_sum = 0.0;
}

__global__ void k_count(const int* __restrict__ ei, const float* __restrict__ eattr) {
    int e = blockIdx.x * blockDim.x + threadIdx.x;
    float v = 0.f;
    if (e < NE) {
        atomicAdd(&d_deg[ei[NE + e]], 1);
        v = eattr[e];
    }
    for (int o = 16; o; o >>= 1) v += __shfl_xor_sync(0xffffffffu, v, o);
    __shared__ float ws[8];
    int lane = threadIdx.x & 31, wid = threadIdx.x >> 5;
    if (lane == 0) ws[wid] = v;
    __syncthreads();
    if (threadIdx.x == 0) {
        float s = 0.f;
        for (int w = 0; w < (int)(blockDim.x >> 5); w++) s += ws[w];
        atomicAdd(&d_attr_sum, (double)s);
    }
}

// single-block exclusive scan of degrees -> rowptr; also place self-loop in slot 0
__global__ void k_scan() {
    __shared__ int wsum[32];
    __shared__ int s_carry;
    int t = threadIdx.x, lane = t & 31, wid = t >> 5;
    if (t == 0) s_carry = 0;
    __syncthreads();
    float mean = (float)(d_attr_sum / (double)NE);
    for (int base = 0; base < NN; base += 1024) {
        int n = base + t;
        int orig = (n < NN) ? d_deg[n] : 0;
        int v = orig;
        for (int o = 1; o < 32; o <<= 1) {
            int y = __shfl_up_sync(0xffffffffu, v, o);
            if (lane >= o) v += y;
        }
        if (lane == 31) wsum[wid] = v;
        __syncthreads();
        if (wid == 0) {
            int w = wsum[lane];
            for (int o = 1; o < 32; o <<= 1) {
                int y = __shfl_up_sync(0xffffffffu, w, o);
                if (lane >= o) w += y;
            }
            wsum[lane] = w;
        }
        __syncthreads();
        int start = s_carry + v + (wid ? wsum[wid - 1] : 0) - orig;
        int total = wsum[31];
        if (n < NN) {
            d_rowptr[n] = start;
            d_next[n]   = start + 1;
            d_csr[start] = make_int2(n, __float_as_int(mean));   // self-loop
        }
        __syncthreads();
        if (t == 0) s_carry += total;
        __syncthreads();
    }
    if (t == 0) d_rowptr[NN] = s_carry;
}

__global__ void k_fill(const int* __restrict__ ei, const float* __restrict__ eattr) {
    int e = blockIdx.x * blockDim.x + threadIdx.x;
    if (e >= NE) return;
    int src = ei[e], dst = ei[NE + e];
    int slot = atomicAdd(&d_next[dst], 1);
    d_csr[slot] = make_int2(src, __float_as_int(eattr[e]));
}

// ---------------- fp32 GEMM: O[rows,ncols] = A[rows,128] @ W[128,ncols] + bias ----------------
#define ASTRIDE 132
__global__ void __launch_bounds__(256) k_gemm(const float* __restrict__ A,
                                              const float* __restrict__ W,
                                              const float* __restrict__ bias,
                                              float* __restrict__ O,
                                              int rows, int ncols) {
    extern __shared__ float sm[];
    float* Ash = sm;                   // 128 x ASTRIDE
    float* Wsh = sm + 128 * ASTRIDE;   // 128 x 64
    int t  = threadIdx.x;
    int rb = blockIdx.x * 128, cb = blockIdx.y * 64;

    const float4* A4 = (const float4*)A;
    for (int i = t; i < 128 * 32; i += 256) {
        int r = i >> 5, c4 = i & 31;
        int gr = rb + r;
        float4 v = (gr < rows) ? A4[gr * 32 + c4] : make_float4(0.f, 0.f, 0.f, 0.f);
        *(float4*)&Ash[r * ASTRIDE + c4 * 4] = v;
    }
    for (int i = t; i < 128 * 16; i += 256) {
        int k = i >> 4, c4 = i & 15;
        *(float4*)&Wsh[k * 64 + c4 * 4] = *(const float4*)&W[k * ncols + cb + c4 * 4];
    }
    __syncthreads();

    int tc = t & 15, tr = t >> 4;
    float acc[8][4];
#pragma unroll
    for (int r = 0; r < 8; r++)
#pragma unroll
        for (int c = 0; c < 4; c++) acc[r][c] = 0.f;

#pragma unroll 4
    for (int k = 0; k < 128; k++) {
        float4 wv = *(float4*)&Wsh[k * 64 + tc * 4];
#pragma unroll
        for (int r = 0; r < 8; r++) {
            float av = Ash[(tr * 8 + r) * ASTRIDE + k];
            acc[r][0] += av * wv.x;
            acc[r][1] += av * wv.y;
            acc[r][2] += av * wv.z;
            acc[r][3] += av * wv.w;
        }
    }

    float4 bv = *(const float4*)&bias[cb + tc * 4];
#pragma unroll
    for (int r = 0; r < 8; r++) {
        int row = rb + tr * 8 + r;
        if (row < rows) {
            float4 o = make_float4(acc[r][0] + bv.x, acc[r][1] + bv.y,
                                   acc[r][2] + bv.z, acc[r][3] + bv.w);
            *(float4*)&O[row * ncols + cb + tc * 4] = o;
        }
    }
}

// ---------------- GATv2 layer 1: heads=4, D=32, concat, ELU ----------------
// one warp per destination node; lane l owns head l>>3, dims 4*(l&7)..+3 (== float4 lane l).
// Single-pass online softmax; per-head reduce = 3 butterflies within 8-lane octets.
__global__ void __launch_bounds__(256) k_gat1(const float* __restrict__ xl,
                                              const float* __restrict__ xr,
                                              const float* __restrict__ we,
                                              const float* __restrict__ att,
                                              const float* __restrict__ bias,
                                              float* __restrict__ out) {
    int w = (blockIdx.x * blockDim.x + threadIdx.x) >> 5;
    if (w >= NN) return;
    int lane = threadIdx.x & 31;
    int n = w;

    float4 xr4  = ((const float4*)(xr + (size_t)n * 128))[lane];
    float4 we4  = __ldg((const float4*)we  + lane);
    float4 att4 = __ldg((const float4*)att + lane);

    int d0 = d_rowptr[n], d1 = d_rowptr[n + 1];

    float mx = -1e30f, den = 0.f;
    float4 acc = make_float4(0.f, 0.f, 0.f, 0.f);

    int2 e = d_csr[d0];
    for (int i = d0; i < d1; i++) {
        int   s   = e.x;
        float eav = __int_as_float(e.y);
        if (i + 1 < d1) e = d_csr[i + 1];
        float4 xlv = __ldg((const float4*)(xl + (size_t)s * 128) + lane);

        float zx = xlv.x + xr4.x + eav * we4.x;  zx = fmaxf(zx, 0.2f * zx);
        float zy = xlv.y + xr4.y + eav * we4.y;  zy = fmaxf(zy, 0.2f * zy);
        float zz = xlv.z + xr4.z + eav * we4.z;  zz = fmaxf(zz, 0.2f * zz);
        float zw = xlv.w + xr4.w + eav * we4.w;  zw = fmaxf(zw, 0.2f * zw);
        float v = zx * att4.x + zy * att4.y + zz * att4.z + zw * att4.w;
        v += __shfl_xor_sync(0xffffffffu, v, 4);
        v += __shfl_xor_sync(0xffffffffu, v, 2);
        v += __shfl_xor_sync(0xffffffffu, v, 1);   // v = full head score (all octet lanes)

        float nm = fmaxf(mx, v);
        float sc = __expf(mx - nm);    // 0 on first edge (mx=-1e30), 1 when max unchanged
        float ex = __expf(v - nm);
        den = den * sc + ex;
        acc.x = acc.x * sc + ex * xlv.x;
        acc.y = acc.y * sc + ex * xlv.y;
        acc.z = acc.z * sc + ex * xlv.z;
        acc.w = acc.w * sc + ex * xlv.w;
        mx = nm;
    }

    float inv = 1.f / den;
    float4 b4 = __ldg((const float4*)bias + lane);
    float4 o;
    o.x = acc.x * inv + b4.x;  o.x = (o.x > 0.f) ? o.x : expm1f(o.x);
    o.y = acc.y * inv + b4.y;  o.y = (o.y > 0.f) ? o.y : expm1f(o.y);
    o.z = acc.z * inv + b4.z;  o.z = (o.z > 0.f) ? o.z : expm1f(o.z);
    o.w = acc.w * inv + b4.w;  o.w = (o.w > 0.f) ? o.w : expm1f(o.w);
    ((float4*)(out + (size_t)n * 128))[lane] = o;
}

// ---------------- GATv2 layer 2 (heads=2, mean) + ELU + classifier, fused ----------------
// lane l owns head l>>4, dims 2*(l&15)..+1 (== float2 lane l). Reduce = 4 butterflies / 16 lanes.
__global__ void __launch_bounds__(256) k_gat2(const float* __restrict__ xl,
                                              const float* __restrict__ xr,
                                              const float* __restrict__ we,
                                              const float* __restrict__ att,
                                              const float* __restrict__ bias,
                                              const float* __restrict__ wc,
                                              const float* __restrict__ bc,
                                              float* __restrict__ out) {
    int w = (blockIdx.x * blockDim.x + threadIdx.x) >> 5;
    if (w >= NN) return;
    int lane = threadIdx.x & 31;
    int n = w;

    float2 xr2  = ((const float2*)(xr + (size_t)n * 64))[lane];
    float2 we2  = __ldg((const float2*)we  + lane);
    float2 att2 = __ldg((const float2*)att + lane);

    int d0 = d_rowptr[n], d1 = d_rowptr[n + 1];

    float mx = -1e30f, den = 0.f;
    float2 acc = make_float2(0.f, 0.f);

    int2 e = d_csr[d0];
    for (int i = d0; i < d1; i++) {
        int   s   = e.x;
        float eav = __int_as_float(e.y);
        if (i + 1 < d1) e = d_csr[i + 1];
        float2 xlv = __ldg((const float2*)(xl + (size_t)s * 64) + lane);

        float zx = xlv.x + xr2.x + eav * we2.x;  zx = fmaxf(zx, 0.2f * zx);
        float zy = xlv.y + xr2.y + eav * we2.y;  zy = fmaxf(zy, 0.2f * zy);
        float v = zx * att2.x + zy * att2.y;
        v += __shfl_xor_sync(0xffffffffu, v, 8);
        v += __shfl_xor_sync(0xffffffffu, v, 4);
        v += __shfl_xor_sync(0xffffffffu, v, 2);
        v += __shfl_xor_sync(0xffffffffu, v, 1);

        float nm = fmaxf(mx, v);
        float sc = __expf(mx - nm);
        float ex = __expf(v - nm);
        den = den * sc + ex;
        acc.x = acc.x * sc + ex * xlv.x;
        acc.y = acc.y * sc + ex * xlv.y;
        mx = nm;
    }

    float inv = 1.f / den;
    float m0 = acc.x * inv, m1 = acc.y * inv;
    // mean over heads: combine lane l with lane l^16 (xor butterfly -> both sides get sum)
    m0 = 0.5f * (m0 + __shfl_xor_sync(0xffffffffu, m0, 16));
    m1 = 0.5f * (m1 + __shfl_xor_sync(0xffffffffu, m1, 16));

    int dl = lane & 15;                       // dims 2*dl, 2*dl+1
    float2 b2 = __ldg((const float2*)bias + dl);
    float t0 = m0 + b2.x;  t0 = (t0 > 0.f) ? t0 : expm1f(t0);
    float t1 = m1 + b2.y;  t1 = (t1 > 0.f) ? t1 : expm1f(t1);

    // classifier: wc is (32, 8). Lanes 16..31 duplicate lanes 0..15 -> halve after reduce.
    float4 wA0 = __ldg((const float4*)wc + dl * 4 + 0);   // wc[2*dl][0..3]
    float4 wA1 = __ldg((const float4*)wc + dl * 4 + 1);   // wc[2*dl][4..7]
    float4 wB0 = __ldg((const float4*)wc + dl * 4 + 2);   // wc[2*dl+1][0..3]
    float4 wB1 = __ldg((const float4*)wc + dl * 4 + 3);   // wc[2*dl+1][4..7]
    float p0 = t0 * wA0.x + t1 * wB0.x;
    float p1 = t0 * wA0.y + t1 * wB0.y;
    float p2 = t0 * wA0.z + t1 * wB0.z;
    float p3 = t0 * wA0.w + t1 * wB0.w;
    float p4 = t0 * wA1.x + t1 * wB1.x;
    float p5 = t0 * wA1.y + t1 * wB1.y;
    float p6 = t0 * wA1.z + t1 * wB1.z;
    float p7 = t0 * wA1.w + t1 * wB1.w;
    for (int o = 16; o; o >>= 1) {
        p0 += __shfl_xor_sync(0xffffffffu, p0, o);
        p1 += __shfl_xor_sync(0xffffffffu, p1, o);
        p2 += __shfl_xor_sync(0xffffffffu, p2, o);
        p3 += __shfl_xor_sync(0xffffffffu, p3, o);
        p4 += __shfl_xor_sync(0xffffffffu, p4, o);
        p5 += __shfl_xor_sync(0xffffffffu, p5, o);
        p6 += __shfl_xor_sync(0xffffffffu, p6, o);
        p7 += __shfl_xor_sync(0xffffffffu, p7, o);
    }
    if (lane == 0) {
        float4 o0 = make_float4(0.5f * p0 + __ldg(bc + 0), 0.5f * p1 + __ldg(bc + 1),
                                0.5f * p2 + __ldg(bc + 2), 0.5f * p3 + __ldg(bc + 3));
        float4 o1 = make_float4(0.5f * p4 + __ldg(bc + 4), 0.5f * p5 + __ldg(bc + 5),
                                0.5f * p6 + __ldg(bc + 6), 0.5f * p7 + __ldg(bc + 7));
        *(float4*)&out[(size_t)n * 8]     = o0;
        *(float4*)&out[(size_t)n * 8 + 4] = o1;
    }
}

// ---------------- launch ----------------
extern "C" void kernel_launch(void* const* d_in, const int* in_sizes, int n_in,
                              void* d_out, int out_size) {
    const float* x     = (const float*)d_in[0];
    const int*   ei    = (const int*)  d_in[1];
    const float* eattr = (const float*)d_in[2];
    const float* w1l   = (const float*)d_in[3];
    const float* b1l   = (const float*)d_in[4];
    const float* w1r   = (const float*)d_in[5];
    const float* b1r   = (const float*)d_in[6];
    const float* w1e   = (const float*)d_in[7];
    const float* att1  = (const float*)d_in[8];
    const float* bias1 = (const float*)d_in[9];
    const float* w2l   = (const float*)d_in[10];
    const float* b2l   = (const float*)d_in[11];
    const float* w2r   = (const float*)d_in[12];
    const float* b2r   = (const float*)d_in[13];
    const float* w2e   = (const float*)d_in[14];
    const float* att2  = (const float*)d_in[15];
    const float* bias2 = (const float*)d_in[16];
    const float* wc    = (const float*)d_in[17];
    const float* bc    = (const float*)d_in[18];
    float* out = (float*)d_out;

    void *pxl1, *pxr1, *ph1, *pxl2, *pxr2;
    cudaGetSymbolAddress(&pxl1, d_xl1);
    cudaGetSymbolAddress(&pxr1, d_xr1);
    cudaGetSymbolAddress(&ph1,  d_h1);
    cudaGetSymbolAddress(&pxl2, d_xl2);
    cudaGetSymbolAddress(&pxr2, d_xr2);

    k_init <<<(NN + 255) / 256, 256>>>();
    k_count<<<(NE + 255) / 256, 256>>>(ei, eattr);
    k_scan <<<1, 1024>>>();
    k_fill <<<(NE + 255) / 256, 256>>>(ei, eattr);

    size_t smem = (size_t)(128 * ASTRIDE + 128 * 64) * sizeof(float);
    cudaFuncSetAttribute(k_gemm, cudaFuncAttributeMaxDynamicSharedMemorySize, (int)smem);

    dim3 g1((NN + 127) / 128, 2);
    k_gemm<<<g1, 256, smem>>>(x, w1l, b1l, (float*)pxl1, NN, 128);
    k_gemm<<<g1, 256, smem>>>(x, w1r, b1r, (float*)pxr1, NN, 128);

    int gat_blocks = (NN * 32 + 255) / 256;
    k_gat1<<<gat_blocks, 256>>>((const float*)pxl1, (const float*)pxr1,
                                w1e, att1, bias1, (float*)ph1);

    dim3 g2((NN + 127) / 128, 1);
    k_gemm<<<g2, 256, smem>>>((const float*)ph1, w2l, b2l, (float*)pxl2, NN, 64);
    k_gemm<<<g2, 256, smem>>>((const float*)ph1, w2r, b2r, (float*)pxr2, NN, 64);

    k_gat2<<<gat_blocks, 256>>>((const float*)pxl2, (const float*)pxr2,
                                w2e, att2, bias2, wc, bc, out);
}

// round 5
// speedup vs baseline: 1.6800x; 1.0722x over previous
#include <cuda_runtime.h>

#define NN 50000
#define NE 800000
#define NET (NN + NE)
#define NB  ((NN + 255) / 256)

typedef unsigned long long ull;

// ---------------- scratch (no allocs allowed) ----------------
__device__ int    d_deg[NN];
__device__ int    d_rowptr[NN + 1];
__device__ int    d_next[NN];
__device__ int    d_part[NB];
__device__ __align__(16) int2 d_csr[NET];      // {src, float_bits(edge_attr)}
__device__ double d_attr_sum;

__device__ __align__(16) float d_xl1[NN * 128];
__device__ __align__(16) float d_xr1[NN * 128];
__device__ __align__(16) float d_h1 [NN * 128];
__device__ __align__(16) float d_xl2[NN * 64];
__device__ __align__(16) float d_xr2[NN * 64];

// packed f32x2 fma: d.lo += a.lo*b.lo ; d.hi += a.hi*b.hi  (fp32 exact)
#define FMA2(d, a, b) asm("fma.rn.f32x2 %0, %1, %2, %0;" : "+l"(d) : "l"(a), "l"(b))
#define UNPACK2(lo, hi, p) asm("mov.b64 {%0, %1}, %2;" : "=f"(lo), "=f"(hi) : "l"(p))

// ---------------- CSR build ----------------
__global__ void k_init() {
    int i = blockIdx.x * blockDim.x + threadIdx.x;
    if (i < NN) d_deg[i] = 1;           // slot 0 of each node = its self-loop
    if (i == 0) d_attr_sum = 0.0;
}

__global__ void k_count(const int* __restrict__ ei, const float* __restrict__ eattr) {
    int e = blockIdx.x * blockDim.x + threadIdx.x;
    float v = 0.f;
    if (e < NE) {
        atomicAdd(&d_deg[ei[NE + e]], 1);
        v = eattr[e];
    }
    for (int o = 16; o; o >>= 1) v += __shfl_xor_sync(0xffffffffu, v, o);
    __shared__ float ws[8];
    int lane = threadIdx.x & 31, wid = threadIdx.x >> 5;
    if (lane == 0) ws[wid] = v;
    __syncthreads();
    if (threadIdx.x == 0) {
        float s = 0.f;
        for (int w = 0; w < (int)(blockDim.x >> 5); w++) s += ws[w];
        atomicAdd(&d_attr_sum, (double)s);
    }
}

// two-level scan: per-block sums -> scan of sums -> per-block exclusive scan
__global__ void k_scan1() {
    int n = blockIdx.x * 256 + threadIdx.x;
    int v = (n < NN) ? d_deg[n] : 0;
    for (int o = 16; o; o >>= 1) v += __shfl_xor_sync(0xffffffffu, v, o);
    __shared__ int ws[8];
    int lane = threadIdx.x & 31, wid = threadIdx.x >> 5;
    if (lane == 0) ws[wid] = v;
    __syncthreads();
    if (threadIdx.x == 0) {
        int s = 0;
        for (int w = 0; w < 8; w++) s += ws[w];
        d_part[blockIdx.x] = s;
    }
}

__global__ void k_scan2() {   // single block, 256 threads; NB <= 256
    int t = threadIdx.x, lane = t & 31, wid = t >> 5;
    int v = (t < NB) ? d_part[t] : 0;
    int inc = v;
    for (int o = 1; o < 32; o <<= 1) {
        int y = __shfl_up_sync(0xffffffffu, inc, o);
        if (lane >= o) inc += y;
    }
    __shared__ int ws[8];
    if (lane == 31) ws[wid] = inc;
    __syncthreads();
    if (wid == 0) {
        int w = (lane < 8) ? ws[lane] : 0;
        for (int o = 1; o < 8; o <<= 1) {
            int y = __shfl_up_sync(0xffffffffu, w, o);
            if (lane >= o) w += y;
        }
        if (lane < 8) ws[lane] = w;
    }
    __syncthreads();
    int excl = inc - v + (wid ? ws[wid - 1] : 0);
    if (t < NB) d_part[t] = excl;
    if (t == 0) d_rowptr[NN] = ws[7];
}

__global__ void k_scan3() {
    int b = blockIdx.x, t = threadIdx.x, lane = t & 31, wid = t >> 5;
    int n = b * 256 + t;
    int orig = (n < NN) ? d_deg[n] : 0;
    int inc = orig;
    for (int o = 1; o < 32; o <<= 1) {
        int y = __shfl_up_sync(0xffffffffu, inc, o);
        if (lane >= o) inc += y;
    }
    __shared__ int ws[8];
    if (lane == 31) ws[wid] = inc;
    __syncthreads();
    if (wid == 0) {
        int w = (lane < 8) ? ws[lane] : 0;
        for (int o = 1; o < 8; o <<= 1) {
            int y = __shfl_up_sync(0xffffffffu, w, o);
            if (lane >= o) w += y;
        }
        if (lane < 8) ws[lane] = w;
    }
    __syncthreads();
    if (n < NN) {
        int start = d_part[b] + inc - orig + (wid ? ws[wid - 1] : 0);
        float mean = (float)(d_attr_sum / (double)NE);
        d_rowptr[n] = start;
        d_next[n]   = start + 1;
        d_csr[start] = make_int2(n, __float_as_int(mean));   // self-loop
    }
}

__global__ void k_fill(const int* __restrict__ ei, const float* __restrict__ eattr) {
    int e = blockIdx.x * blockDim.x + threadIdx.x;
    if (e >= NE) return;
    int src = ei[e], dst = ei[NE + e];
    int slot = atomicAdd(&d_next[dst], 1);
    d_csr[slot] = make_int2(src, __float_as_int(eattr[e]));
}

// ---------------- fp32 GEMM via packed f32x2 FMA ----------------
// O[rows,ncols] = A[rows,128] @ W[128,ncols] + bias
// block tile 128x64, thread tile 8x4. Packed pair = (k even, k odd); per-half
// partial sums combined in the epilogue. A staged row-major (k contiguous ->
// LDS.64 pairs, lane-broadcast); W staged transposed (k contiguous per col).
#define ASTRIDE 132
#define WTSTRIDE 130
__global__ void __launch_bounds__(256) k_gemm(const float* __restrict__ A,
                                              const float* __restrict__ W,
                                              const float* __restrict__ bias,
                                              float* __restrict__ O,
                                              int rows, int ncols) {
    extern __shared__ float sm[];
    float* Ash  = sm;                    // 128 x ASTRIDE  (row x k)
    float* WshT = sm + 128 * ASTRIDE;    // 64  x WTSTRIDE (col x k)
    int t  = threadIdx.x;
    int rb = blockIdx.x * 128, cb = blockIdx.y * 64;

    const float4* A4 = (const float4*)A;
    for (int i = t; i < 128 * 32; i += 256) {
        int r = i >> 5, c4 = i & 31;
        int gr = rb + r;
        float4 v = (gr < rows) ? A4[gr * 32 + c4] : make_float4(0.f, 0.f, 0.f, 0.f);
        *(float4*)&Ash[r * ASTRIDE + c4 * 4] = v;
    }
    for (int i = t; i < 128 * 16; i += 256) {
        int k = i >> 4, c4 = i & 15;
        float4 v = *(const float4*)&W[k * ncols + cb + c4 * 4];
        WshT[(c4 * 4 + 0) * WTSTRIDE + k] = v.x;
        WshT[(c4 * 4 + 1) * WTSTRIDE + k] = v.y;
        WshT[(c4 * 4 + 2) * WTSTRIDE + k] = v.z;
        WshT[(c4 * 4 + 3) * WTSTRIDE + k] = v.w;
    }
    __syncthreads();

    int tc = t & 15, tr = t >> 4;
    const float* arow = &Ash[(tr * 8) * ASTRIDE];
    const float* wcol = &WshT[(tc * 4) * WTSTRIDE];

    ull acc[8][4];
#pragma unroll
    for (int r = 0; r < 8; r++)
#pragma unroll
        for (int c = 0; c < 4; c++) acc[r][c] = 0ULL;

#pragma unroll 4
    for (int k2 = 0; k2 < 64; k2++) {
        ull wv[4];
#pragma unroll
        for (int c = 0; c < 4; c++)
            wv[c] = *(const ull*)&wcol[c * WTSTRIDE + 2 * k2];
#pragma unroll
        for (int r = 0; r < 8; r++) {
            ull av = *(const ull*)&arow[r * ASTRIDE + 2 * k2];
            FMA2(acc[r][0], av, wv[0]);
            FMA2(acc[r][1], av, wv[1]);
            FMA2(acc[r][2], av, wv[2]);
            FMA2(acc[r][3], av, wv[3]);
        }
    }

    float4 bv = *(const float4*)&bias[cb + tc * 4];
#pragma unroll
    for (int r = 0; r < 8; r++) {
        int row = rb + tr * 8 + r;
        if (row < rows) {
            float lo, hi;
            float4 o;
            UNPACK2(lo, hi, acc[r][0]);  o.x = lo + hi + bv.x;
            UNPACK2(lo, hi, acc[r][1]);  o.y = lo + hi + bv.y;
            UNPACK2(lo, hi, acc[r][2]);  o.z = lo + hi + bv.z;
            UNPACK2(lo, hi, acc[r][3]);  o.w = lo + hi + bv.w;
            *(float4*)&O[row * ncols + cb + tc * 4] = o;
        }
    }
}

// ---------------- GATv2 layer 1: heads=4, D=32, concat, ELU ----------------
__global__ void __launch_bounds__(256) k_gat1(const float* __restrict__ xl,
                                              const float* __restrict__ xr,
                                              const float* __restrict__ we,
                                              const float* __restrict__ att,
                                              const float* __restrict__ bias,
                                              float* __restrict__ out) {
    int w = (blockIdx.x * blockDim.x + threadIdx.x) >> 5;
    if (w >= NN) return;
    int lane = threadIdx.x & 31;
    int n = w;

    float4 xr4  = ((const float4*)(xr + (size_t)n * 128))[lane];
    float4 we4  = __ldg((const float4*)we  + lane);
    float4 att4 = __ldg((const float4*)att + lane);

    int d0 = d_rowptr[n], d1 = d_rowptr[n + 1];

    float mx = -1e30f, den = 0.f;
    float4 acc = make_float4(0.f, 0.f, 0.f, 0.f);

    int2 e = d_csr[d0];
    for (int i = d0; i < d1; i++) {
        int   s   = e.x;
        float eav = __int_as_float(e.y);
        if (i + 1 < d1) e = d_csr[i + 1];
        float4 xlv = __ldg((const float4*)(xl + (size_t)s * 128) + lane);

        float zx = xlv.x + xr4.x + eav * we4.x;  zx = fmaxf(zx, 0.2f * zx);
        float zy = xlv.y + xr4.y + eav * we4.y;  zy = fmaxf(zy, 0.2f * zy);
        float zz = xlv.z + xr4.z + eav * we4.z;  zz = fmaxf(zz, 0.2f * zz);
        float zw = xlv.w + xr4.w + eav * we4.w;  zw = fmaxf(zw, 0.2f * zw);
        float v = zx * att4.x + zy * att4.y + zz * att4.z + zw * att4.w;
        v += __shfl_xor_sync(0xffffffffu, v, 4);
        v += __shfl_xor_sync(0xffffffffu, v, 2);
        v += __shfl_xor_sync(0xffffffffu, v, 1);

        float nm = fmaxf(mx, v);
        float sc = __expf(mx - nm);
        float ex = __expf(v - nm);
        den = den * sc + ex;
        acc.x = acc.x * sc + ex * xlv.x;
        acc.y = acc.y * sc + ex * xlv.y;
        acc.z = acc.z * sc + ex * xlv.z;
        acc.w = acc.w * sc + ex * xlv.w;
        mx = nm;
    }

    float inv = 1.f / den;
    float4 b4 = __ldg((const float4*)bias + lane);
    float4 o;
    o.x = acc.x * inv + b4.x;  o.x = (o.x > 0.f) ? o.x : expm1f(o.x);
    o.y = acc.y * inv + b4.y;  o.y = (o.y > 0.f) ? o.y : expm1f(o.y);
    o.z = acc.z * inv + b4.z;  o.z = (o.z > 0.f) ? o.z : expm1f(o.z);
    o.w = acc.w * inv + b4.w;  o.w = (o.w > 0.f) ? o.w : expm1f(o.w);
    ((float4*)(out + (size_t)n * 128))[lane] = o;
}

// ---------------- GATv2 layer 2 (heads=2, mean) + ELU + classifier, fused ----------------
__global__ void __launch_bounds__(256) k_gat2(const float* __restrict__ xl,
                                              const float* __restrict__ xr,
                                              const float* __restrict__ we,
                                              const float* __restrict__ att,
                                              const float* __restrict__ bias,
                                              const float* __restrict__ wc,
                                              const float* __restrict__ bc,
                                              float* __restrict__ out) {
    int w = (blockIdx.x * blockDim.x + threadIdx.x) >> 5;
    if (w >= NN) return;
    int lane = threadIdx.x & 31;
    int n = w;

    float2 xr2  = ((const float2*)(xr + (size_t)n * 64))[lane];
    float2 we2  = __ldg((const float2*)we  + lane);
    float2 att2 = __ldg((const float2*)att + lane);

    int d0 = d_rowptr[n], d1 = d_rowptr[n + 1];

    float mx = -1e30f, den = 0.f;
    float2 acc = make_float2(0.f, 0.f);

    int2 e = d_csr[d0];
    for (int i = d0; i < d1; i++) {
        int   s   = e.x;
        float eav = __int_as_float(e.y);
        if (i + 1 < d1) e = d_csr[i + 1];
        float2 xlv = __ldg((const float2*)(xl + (size_t)s * 64) + lane);

        float zx = xlv.x + xr2.x + eav * we2.x;  zx = fmaxf(zx, 0.2f * zx);
        float zy = xlv.y + xr2.y + eav * we2.y;  zy = fmaxf(zy, 0.2f * zy);
        float v = zx * att2.x + zy * att2.y;
        v += __shfl_xor_sync(0xffffffffu, v, 8);
        v += __shfl_xor_sync(0xffffffffu, v, 4);
        v += __shfl_xor_sync(0xffffffffu, v, 2);
        v += __shfl_xor_sync(0xffffffffu, v, 1);

        float nm = fmaxf(mx, v);
        float sc = __expf(mx - nm);
        float ex = __expf(v - nm);
        den = den * sc + ex;
        acc.x = acc.x * sc + ex * xlv.x;
        acc.y = acc.y * sc + ex * xlv.y;
        mx = nm;
    }

    float inv = 1.f / den;
    float m0 = acc.x * inv, m1 = acc.y * inv;
    m0 = 0.5f * (m0 + __shfl_xor_sync(0xffffffffu, m0, 16));
    m1 = 0.5f * (m1 + __shfl_xor_sync(0xffffffffu, m1, 16));

    int dl = lane & 15;
    float2 b2 = __ldg((const float2*)bias + dl);
    float t0 = m0 + b2.x;  t0 = (t0 > 0.f) ? t0 : expm1f(t0);
    float t1 = m1 + b2.y;  t1 = (t1 > 0.f) ? t1 : expm1f(t1);

    float4 wA0 = __ldg((const float4*)wc + dl * 4 + 0);
    float4 wA1 = __ldg((const float4*)wc + dl * 4 + 1);
    float4 wB0 = __ldg((const float4*)wc + dl * 4 + 2);
    float4 wB1 = __ldg((const float4*)wc + dl * 4 + 3);
    float p0 = t0 * wA0.x + t1 * wB0.x;
    float p1 = t0 * wA0.y + t1 * wB0.y;
    float p2 = t0 * wA0.z + t1 * wB0.z;
    float p3 = t0 * wA0.w + t1 * wB0.w;
    float p4 = t0 * wA1.x + t1 * wB1.x;
    float p5 = t0 * wA1.y + t1 * wB1.y;
    float p6 = t0 * wA1.z + t1 * wB1.z;
    float p7 = t0 * wA1.w + t1 * wB1.w;
    for (int o = 16; o; o >>= 1) {
        p0 += __shfl_xor_sync(0xffffffffu, p0, o);
        p1 += __shfl_xor_sync(0xffffffffu, p1, o);
        p2 += __shfl_xor_sync(0xffffffffu, p2, o);
        p3 += __shfl_xor_sync(0xffffffffu, p3, o);
        p4 += __shfl_xor_sync(0xffffffffu, p4, o);
        p5 += __shfl_xor_sync(0xffffffffu, p5, o);
        p6 += __shfl_xor_sync(0xffffffffu, p6, o);
        p7 += __shfl_xor_sync(0xffffffffu, p7, o);
    }
    if (lane == 0) {
        float4 o0 = make_float4(0.5f * p0 + __ldg(bc + 0), 0.5f * p1 + __ldg(bc + 1),
                                0.5f * p2 + __ldg(bc + 2), 0.5f * p3 + __ldg(bc + 3));
        float4 o1 = make_float4(0.5f * p4 + __ldg(bc + 4), 0.5f * p5 + __ldg(bc + 5),
                                0.5f * p6 + __ldg(bc + 6), 0.5f * p7 + __ldg(bc + 7));
        *(float4*)&out[(size_t)n * 8]     = o0;
        *(float4*)&out[(size_t)n * 8 + 4] = o1;
    }
}

// ---------------- launch ----------------
extern "C" void kernel_launch(void* const* d_in, const int* in_sizes, int n_in,
                              void* d_out, int out_size) {
    const float* x     = (const float*)d_in[0];
    const int*   ei    = (const int*)  d_in[1];
    const float* eattr = (const float*)d_in[2];
    const float* w1l   = (const float*)d_in[3];
    const float* b1l   = (const float*)d_in[4];
    const float* w1r   = (const float*)d_in[5];
    const float* b1r   = (const float*)d_in[6];
    const float* w1e   = (const float*)d_in[7];
    const float* att1  = (const float*)d_in[8];
    const float* bias1 = (const float*)d_in[9];
    const float* w2l   = (const float*)d_in[10];
    const float* b2l   = (const float*)d_in[11];
    const float* w2r   = (const float*)d_in[12];
    const float* b2r   = (const float*)d_in[13];
    const float* w2e   = (const float*)d_in[14];
    const float* att2  = (const float*)d_in[15];
    const float* bias2 = (const float*)d_in[16];
    const float* wc    = (const float*)d_in[17];
    const float* bc    = (const float*)d_in[18];
    float* out = (float*)d_out;

    void *pxl1, *pxr1, *ph1, *pxl2, *pxr2;
    cudaGetSymbolAddress(&pxl1, d_xl1);
    cudaGetSymbolAddress(&pxr1, d_xr1);
    cudaGetSymbolAddress(&ph1,  d_h1);
    cudaGetSymbolAddress(&pxl2, d_xl2);
    cudaGetSymbolAddress(&pxr2, d_xr2);

    k_init <<<(NN + 255) / 256, 256>>>();
    k_count<<<(NE + 255) / 256, 256>>>(ei, eattr);
    k_scan1<<<NB, 256>>>();
    k_scan2<<<1, 256>>>();
    k_scan3<<<NB, 256>>>();
    k_fill <<<(NE + 255) / 256, 256>>>(ei, eattr);

    size_t smem = (size_t)(128 * ASTRIDE + 64 * WTSTRIDE) * sizeof(float);
    cudaFuncSetAttribute(k_gemm, cudaFuncAttributeMaxDynamicSharedMemorySize, (int)smem);

    dim3 g1((NN + 127) / 128, 2);
    k_gemm<<<g1, 256, smem>>>(x, w1l, b1l, (float*)pxl1, NN, 128);
    k_gemm<<<g1, 256, smem>>>(x, w1r, b1r, (float*)pxr1, NN, 128);

    int gat_blocks = (NN * 32 + 255) / 256;
    k_gat1<<<gat_blocks, 256>>>((const float*)pxl1, (const float*)pxr1,
                                w1e, att1, bias1, (float*)ph1);

    dim3 g2((NN + 127) / 128, 1);
    k_gemm<<<g2, 256, smem>>>((const float*)ph1, w2l, b2l, (float*)pxl2, NN, 64);
    k_gemm<<<g2, 256, smem>>>((const float*)ph1, w2r, b2r, (float*)pxr2, NN, 64);

    k_gat2<<<gat_blocks, 256>>>((const float*)pxl2, (const float*)pxr2,
                                w2e, att2, bias2, wc, bc, out);
}

// round 6
// speedup vs baseline: 1.9049x; 1.1339x over previous
#include <cuda_runtime.h>

#define NN 50000
#define NE 800000
#define NET (NN + NE)
#define NB  ((NN + 255) / 256)

typedef unsigned long long ull;

// ---------------- scratch (no allocs allowed) ----------------
__device__ int    d_deg[NN];
__device__ int    d_rowptr[NN + 1];
__device__ int    d_next[NN];
__device__ int    d_part[NB];
__device__ __align__(16) int2 d_csr[NET];      // {src, float_bits(edge_attr)}
__device__ double d_attr_sum;

__device__ __align__(16) float d_xl1[NN * 128];
__device__ __align__(16) float d_xr1[NN * 128];
__device__ __align__(16) float d_h1 [NN * 128];
__device__ __align__(16) float d_xl2[NN * 64];
__device__ __align__(16) float d_xr2[NN * 64];

// packed f32x2 fma: d.lo += a.lo*b.lo ; d.hi += a.hi*b.hi  (fp32 exact)
#define FMA2(d, a, b) asm("fma.rn.f32x2 %0, %1, %2, %0;" : "+l"(d) : "l"(a), "l"(b))
#define UNPACK2(lo, hi, p) asm("mov.b64 {%0, %1}, %2;" : "=f"(lo), "=f"(hi) : "l"(p))

// ---------------- CSR build ----------------
__global__ void k_init() {
    int i = blockIdx.x * blockDim.x + threadIdx.x;
    if (i < NN) d_deg[i] = 1;           // slot 0 of each node = its self-loop
    if (i == 0) d_attr_sum = 0.0;
}

__global__ void k_count(const int* __restrict__ ei, const float* __restrict__ eattr) {
    int e = blockIdx.x * blockDim.x + threadIdx.x;
    float v = 0.f;
    if (e < NE) {
        atomicAdd(&d_deg[ei[NE + e]], 1);
        v = eattr[e];
    }
    for (int o = 16; o; o >>= 1) v += __shfl_xor_sync(0xffffffffu, v, o);
    __shared__ float ws[8];
    int lane = threadIdx.x & 31, wid = threadIdx.x >> 5;
    if (lane == 0) ws[wid] = v;
    __syncthreads();
    if (threadIdx.x == 0) {
        float s = 0.f;
        for (int w = 0; w < (int)(blockDim.x >> 5); w++) s += ws[w];
        atomicAdd(&d_attr_sum, (double)s);
    }
}

// two-level scan: per-block sums -> scan of sums -> per-block exclusive scan
__global__ void k_scan1() {
    int n = blockIdx.x * 256 + threadIdx.x;
    int v = (n < NN) ? d_deg[n] : 0;
    for (int o = 16; o; o >>= 1) v += __shfl_xor_sync(0xffffffffu, v, o);
    __shared__ int ws[8];
    int lane = threadIdx.x & 31, wid = threadIdx.x >> 5;
    if (lane == 0) ws[wid] = v;
    __syncthreads();
    if (threadIdx.x == 0) {
        int s = 0;
        for (int w = 0; w < 8; w++) s += ws[w];
        d_part[blockIdx.x] = s;
    }
}

__global__ void k_scan2() {   // single block, 256 threads; NB <= 256
    int t = threadIdx.x, lane = t & 31, wid = t >> 5;
    int v = (t < NB) ? d_part[t] : 0;
    int inc = v;
    for (int o = 1; o < 32; o <<= 1) {
        int y = __shfl_up_sync(0xffffffffu, inc, o);
        if (lane >= o) inc += y;
    }
    __shared__ int ws[8];
    if (lane == 31) ws[wid] = inc;
    __syncthreads();
    if (wid == 0) {
        int w = (lane < 8) ? ws[lane] : 0;
        for (int o = 1; o < 8; o <<= 1) {
            int y = __shfl_up_sync(0xffffffffu, w, o);
            if (lane >= o) w += y;
        }
        if (lane < 8) ws[lane] = w;
    }
    __syncthreads();
    int excl = inc - v + (wid ? ws[wid - 1] : 0);
    if (t < NB) d_part[t] = excl;
    if (t == 0) d_rowptr[NN] = ws[7];
}

__global__ void k_scan3() {
    int b = blockIdx.x, t = threadIdx.x, lane = t & 31, wid = t >> 5;
    int n = b * 256 + t;
    int orig = (n < NN) ? d_deg[n] : 0;
    int inc = orig;
    for (int o = 1; o < 32; o <<= 1) {
        int y = __shfl_up_sync(0xffffffffu, inc, o);
        if (lane >= o) inc += y;
    }
    __shared__ int ws[8];
    if (lane == 31) ws[wid] = inc;
    __syncthreads();
    if (wid == 0) {
        int w = (lane < 8) ? ws[lane] : 0;
        for (int o = 1; o < 8; o <<= 1) {
            int y = __shfl_up_sync(0xffffffffu, w, o);
            if (lane >= o) w += y;
        }
        if (lane < 8) ws[lane] = w;
    }
    __syncthreads();
    if (n < NN) {
        int start = d_part[b] + inc - orig + (wid ? ws[wid - 1] : 0);
        float mean = (float)(d_attr_sum / (double)NE);
        d_rowptr[n] = start;
        d_next[n]   = start + 1;
        d_csr[start] = make_int2(n, __float_as_int(mean));   // self-loop
    }
}

__global__ void k_fill(const int* __restrict__ ei, const float* __restrict__ eattr) {
    int e = blockIdx.x * blockDim.x + threadIdx.x;
    if (e >= NE) return;
    int src = ei[e], dst = ei[NE + e];
    int slot = atomicAdd(&d_next[dst], 1);
    d_csr[slot] = make_int2(src, __float_as_int(eattr[e]));
}

// ---------------- fused dual fp32 GEMM via packed f32x2 FMA ----------------
// Computes Ol = A@Wl + bl and Or = A@Wr + br in one launch.
// blockIdx.y in [0, 2*ncols/64): first half -> L matrix, second half -> R.
// block tile 128x64, thread tile 8x4. Packed pair = (k even, k odd).
#define ASTRIDE 132
#define WTSTRIDE 130
__global__ void __launch_bounds__(256) k_gemm(const float* __restrict__ A,
                                              const float* __restrict__ Wl,
                                              const float* __restrict__ Wr,
                                              const float* __restrict__ bl,
                                              const float* __restrict__ br,
                                              float* __restrict__ Ol,
                                              float* __restrict__ Or,
                                              int rows, int ncols) {
    extern __shared__ float sm[];
    float* Ash  = sm;                    // 128 x ASTRIDE  (row x k)
    float* WshT = sm + 128 * ASTRIDE;    // 64  x WTSTRIDE (col x k)
    int t  = threadIdx.x;
    int nyh = ncols >> 6;                // y-blocks per matrix
    int half = (int)blockIdx.y >= nyh;
    const float* W    = half ? Wr : Wl;
    const float* bias = half ? br : bl;
    float*       O    = half ? Or : Ol;
    int rb = blockIdx.x * 128;
    int cb = ((int)blockIdx.y - (half ? nyh : 0)) * 64;

    const float4* A4 = (const float4*)A;
    for (int i = t; i < 128 * 32; i += 256) {
        int r = i >> 5, c4 = i & 31;
        int gr = rb + r;
        float4 v = (gr < rows) ? A4[gr * 32 + c4] : make_float4(0.f, 0.f, 0.f, 0.f);
        *(float4*)&Ash[r * ASTRIDE + c4 * 4] = v;
    }
    for (int i = t; i < 128 * 16; i += 256) {
        int k = i >> 4, c4 = i & 15;
        float4 v = *(const float4*)&W[k * ncols + cb + c4 * 4];
        WshT[(c4 * 4 + 0) * WTSTRIDE + k] = v.x;
        WshT[(c4 * 4 + 1) * WTSTRIDE + k] = v.y;
        WshT[(c4 * 4 + 2) * WTSTRIDE + k] = v.z;
        WshT[(c4 * 4 + 3) * WTSTRIDE + k] = v.w;
    }
    __syncthreads();

    int tc = t & 15, tr = t >> 4;
    const float* arow = &Ash[(tr * 8) * ASTRIDE];
    const float* wcol = &WshT[(tc * 4) * WTSTRIDE];

    ull acc[8][4];
#pragma unroll
    for (int r = 0; r < 8; r++)
#pragma unroll
        for (int c = 0; c < 4; c++) acc[r][c] = 0ULL;

#pragma unroll 4
    for (int k2 = 0; k2 < 64; k2++) {
        ull wv[4];
#pragma unroll
        for (int c = 0; c < 4; c++)
            wv[c] = *(const ull*)&wcol[c * WTSTRIDE + 2 * k2];
#pragma unroll
        for (int r = 0; r < 8; r++) {
            ull av = *(const ull*)&arow[r * ASTRIDE + 2 * k2];
            FMA2(acc[r][0], av, wv[0]);
            FMA2(acc[r][1], av, wv[1]);
            FMA2(acc[r][2], av, wv[2]);
            FMA2(acc[r][3], av, wv[3]);
        }
    }

    float4 bv = *(const float4*)&bias[cb + tc * 4];
#pragma unroll
    for (int r = 0; r < 8; r++) {
        int row = rb + tr * 8 + r;
        if (row < rows) {
            float lo, hi;
            float4 o;
            UNPACK2(lo, hi, acc[r][0]);  o.x = lo + hi + bv.x;
            UNPACK2(lo, hi, acc[r][1]);  o.y = lo + hi + bv.y;
            UNPACK2(lo, hi, acc[r][2]);  o.z = lo + hi + bv.z;
            UNPACK2(lo, hi, acc[r][3]);  o.w = lo + hi + bv.w;
            *(float4*)&O[row * ncols + cb + tc * 4] = o;
        }
    }
}

// ---------------- GATv2 layer 1: heads=4, D=32, concat, ELU ----------------
__global__ void __launch_bounds__(256) k_gat1(const float* __restrict__ xl,
                                              const float* __restrict__ xr,
                                              const float* __restrict__ we,
                                              const float* __restrict__ att,
                                              const float* __restrict__ bias,
                                              float* __restrict__ out) {
    int w = (blockIdx.x * blockDim.x + threadIdx.x) >> 5;
    if (w >= NN) return;
    int lane = threadIdx.x & 31;
    int n = w;

    float4 xr4  = ((const float4*)(xr + (size_t)n * 128))[lane];
    float4 we4  = __ldg((const float4*)we  + lane);
    float4 att4 = __ldg((const float4*)att + lane);

    int d0 = d_rowptr[n], d1 = d_rowptr[n + 1];

    float mx = -1e30f, den = 0.f;
    float4 acc = make_float4(0.f, 0.f, 0.f, 0.f);

    int2 e = d_csr[d0];
    for (int i = d0; i < d1; i++) {
        int   s   = e.x;
        float eav = __int_as_float(e.y);
        if (i + 1 < d1) e = d_csr[i + 1];
        float4 xlv = __ldg((const float4*)(xl + (size_t)s * 128) + lane);

        float zx = xlv.x + xr4.x + eav * we4.x;  zx = fmaxf(zx, 0.2f * zx);
        float zy = xlv.y + xr4.y + eav * we4.y;  zy = fmaxf(zy, 0.2f * zy);
        float zz = xlv.z + xr4.z + eav * we4.z;  zz = fmaxf(zz, 0.2f * zz);
        float zw = xlv.w + xr4.w + eav * we4.w;  zw = fmaxf(zw, 0.2f * zw);
        float v = zx * att4.x + zy * att4.y + zz * att4.z + zw * att4.w;
        v += __shfl_xor_sync(0xffffffffu, v, 4);
        v += __shfl_xor_sync(0xffffffffu, v, 2);
        v += __shfl_xor_sync(0xffffffffu, v, 1);

        float nm = fmaxf(mx, v);
        float sc = __expf(mx - nm);
        float ex = __expf(v - nm);
        den = den * sc + ex;
        acc.x = acc.x * sc + ex * xlv.x;
        acc.y = acc.y * sc + ex * xlv.y;
        acc.z = acc.z * sc + ex * xlv.z;
        acc.w = acc.w * sc + ex * xlv.w;
        mx = nm;
    }

    float inv = 1.f / den;
    float4 b4 = __ldg((const float4*)bias + lane);
    float4 o;
    o.x = acc.x * inv + b4.x;  o.x = (o.x > 0.f) ? o.x : expm1f(o.x);
    o.y = acc.y * inv + b4.y;  o.y = (o.y > 0.f) ? o.y : expm1f(o.y);
    o.z = acc.z * inv + b4.z;  o.z = (o.z > 0.f) ? o.z : expm1f(o.z);
    o.w = acc.w * inv + b4.w;  o.w = (o.w > 0.f) ? o.w : expm1f(o.w);
    ((float4*)(out + (size_t)n * 128))[lane] = o;
}

// ---------------- GATv2 layer 2 (heads=2, mean) + ELU + classifier, fused ----------------
__global__ void __launch_bounds__(256) k_gat2(const float* __restrict__ xl,
                                              const float* __restrict__ xr,
                                              const float* __restrict__ we,
                                              const float* __restrict__ att,
                                              const float* __restrict__ bias,
                                              const float* __restrict__ wc,
                                              const float* __restrict__ bc,
                                              float* __restrict__ out) {
    int w = (blockIdx.x * blockDim.x + threadIdx.x) >> 5;
    if (w >= NN) return;
    int lane = threadIdx.x & 31;
    int n = w;

    float2 xr2  = ((const float2*)(xr + (size_t)n * 64))[lane];
    float2 we2  = __ldg((const float2*)we  + lane);
    float2 att2 = __ldg((const float2*)att + lane);

    int d0 = d_rowptr[n], d1 = d_rowptr[n + 1];

    float mx = -1e30f, den = 0.f;
    float2 acc = make_float2(0.f, 0.f);

    int2 e = d_csr[d0];
    for (int i = d0; i < d1; i++) {
        int   s   = e.x;
        float eav = __int_as_float(e.y);
        if (i + 1 < d1) e = d_csr[i + 1];
        float2 xlv = __ldg((const float2*)(xl + (size_t)s * 64) + lane);

        float zx = xlv.x + xr2.x + eav * we2.x;  zx = fmaxf(zx, 0.2f * zx);
        float zy = xlv.y + xr2.y + eav * we2.y;  zy = fmaxf(zy, 0.2f * zy);
        float v = zx * att2.x + zy * att2.y;
        v += __shfl_xor_sync(0xffffffffu, v, 8);
        v += __shfl_xor_sync(0xffffffffu, v, 4);
        v += __shfl_xor_sync(0xffffffffu, v, 2);
        v += __shfl_xor_sync(0xffffffffu, v, 1);

        float nm = fmaxf(mx, v);
        float sc = __expf(mx - nm);
        float ex = __expf(v - nm);
        den = den * sc + ex;
        acc.x = acc.x * sc + ex * xlv.x;
        acc.y = acc.y * sc + ex * xlv.y;
        mx = nm;
    }

    float inv = 1.f / den;
    float m0 = acc.x * inv, m1 = acc.y * inv;
    m0 = 0.5f * (m0 + __shfl_xor_sync(0xffffffffu, m0, 16));
    m1 = 0.5f * (m1 + __shfl_xor_sync(0xffffffffu, m1, 16));

    int dl = lane & 15;
    float2 b2 = __ldg((const float2*)bias + dl);
    float t0 = m0 + b2.x;  t0 = (t0 > 0.f) ? t0 : expm1f(t0);
    float t1 = m1 + b2.y;  t1 = (t1 > 0.f) ? t1 : expm1f(t1);

    float4 wA0 = __ldg((const float4*)wc + dl * 4 + 0);
    float4 wA1 = __ldg((const float4*)wc + dl * 4 + 1);
    float4 wB0 = __ldg((const float4*)wc + dl * 4 + 2);
    float4 wB1 = __ldg((const float4*)wc + dl * 4 + 3);
    float p0 = t0 * wA0.x + t1 * wB0.x;
    float p1 = t0 * wA0.y + t1 * wB0.y;
    float p2 = t0 * wA0.z + t1 * wB0.z;
    float p3 = t0 * wA0.w + t1 * wB0.w;
    float p4 = t0 * wA1.x + t1 * wB1.x;
    float p5 = t0 * wA1.y + t1 * wB1.y;
    float p6 = t0 * wA1.z + t1 * wB1.z;
    float p7 = t0 * wA1.w + t1 * wB1.w;
    for (int o = 16; o; o >>= 1) {
        p0 += __shfl_xor_sync(0xffffffffu, p0, o);
        p1 += __shfl_xor_sync(0xffffffffu, p1, o);
        p2 += __shfl_xor_sync(0xffffffffu, p2, o);
        p3 += __shfl_xor_sync(0xffffffffu, p3, o);
        p4 += __shfl_xor_sync(0xffffffffu, p4, o);
        p5 += __shfl_xor_sync(0xffffffffu, p5, o);
        p6 += __shfl_xor_sync(0xffffffffu, p6, o);
        p7 += __shfl_xor_sync(0xffffffffu, p7, o);
    }
    if (lane == 0) {
        float4 o0 = make_float4(0.5f * p0 + __ldg(bc + 0), 0.5f * p1 + __ldg(bc + 1),
                                0.5f * p2 + __ldg(bc + 2), 0.5f * p3 + __ldg(bc + 3));
        float4 o1 = make_float4(0.5f * p4 + __ldg(bc + 4), 0.5f * p5 + __ldg(bc + 5),
                                0.5f * p6 + __ldg(bc + 6), 0.5f * p7 + __ldg(bc + 7));
        *(float4*)&out[(size_t)n * 8]     = o0;
        *(float4*)&out[(size_t)n * 8 + 4] = o1;
    }
}

// ---------------- launch ----------------
extern "C" void kernel_launch(void* const* d_in, const int* in_sizes, int n_in,
                              void* d_out, int out_size) {
    const float* x     = (const float*)d_in[0];
    const int*   ei    = (const int*)  d_in[1];
    const float* eattr = (const float*)d_in[2];
    const float* w1l   = (const float*)d_in[3];
    const float* b1l   = (const float*)d_in[4];
    const float* w1r   = (const float*)d_in[5];
    const float* b1r   = (const float*)d_in[6];
    const float* w1e   = (const float*)d_in[7];
    const float* att1  = (const float*)d_in[8];
    const float* bias1 = (const float*)d_in[9];
    const float* w2l   = (const float*)d_in[10];
    const float* b2l   = (const float*)d_in[11];
    const float* w2r   = (const float*)d_in[12];
    const float* b2r   = (const float*)d_in[13];
    const float* w2e   = (const float*)d_in[14];
    const float* att2  = (const float*)d_in[15];
    const float* bias2 = (const float*)d_in[16];
    const float* wc    = (const float*)d_in[17];
    const float* bc    = (const float*)d_in[18];
    float* out = (float*)d_out;

    void *pxl1, *pxr1, *ph1, *pxl2, *pxr2;
    cudaGetSymbolAddress(&pxl1, d_xl1);
    cudaGetSymbolAddress(&pxr1, d_xr1);
    cudaGetSymbolAddress(&ph1,  d_h1);
    cudaGetSymbolAddress(&pxl2, d_xl2);
    cudaGetSymbolAddress(&pxr2, d_xr2);

    // side stream + events (created once; reused on every call -> same captured work)
    static cudaStream_t s1 = nullptr;
    static cudaEvent_t ev_fork = nullptr, ev_join = nullptr;
    if (s1 == nullptr) {
        cudaStreamCreateWithFlags(&s1, cudaStreamNonBlocking);
        cudaEventCreateWithFlags(&ev_fork, cudaEventDisableTiming);
        cudaEventCreateWithFlags(&ev_join, cudaEventDisableTiming);
    }

    size_t smem = (size_t)(128 * ASTRIDE + 64 * WTSTRIDE) * sizeof(float);
    cudaFuncSetAttribute(k_gemm, cudaFuncAttributeMaxDynamicSharedMemorySize, (int)smem);

    // fork: CSR build on s1, concurrent with layer-1 GEMM on the main stream
    cudaEventRecord(ev_fork, 0);
    cudaStreamWaitEvent(s1, ev_fork, 0);

    k_init <<<(NN + 255) / 256, 256, 0, s1>>>();
    k_count<<<(NE + 255) / 256, 256, 0, s1>>>(ei, eattr);
    k_scan1<<<NB, 256, 0, s1>>>();
    k_scan2<<<1, 256, 0, s1>>>();
    k_scan3<<<NB, 256, 0, s1>>>();
    k_fill <<<(NE + 255) / 256, 256, 0, s1>>>(ei, eattr);
    cudaEventRecord(ev_join, s1);

    dim3 g1((NN + 127) / 128, 4);   // y: 0-1 -> w1l, 2-3 -> w1r
    k_gemm<<<g1, 256, smem>>>(x, w1l, w1r, b1l, b1r,
                              (float*)pxl1, (float*)pxr1, NN, 128);

    // join: gat1 needs both CSR and the GEMM outputs
    cudaStreamWaitEvent(0, ev_join, 0);

    int gat_blocks = (NN * 32 + 255) / 256;
    k_gat1<<<gat_blocks, 256>>>((const float*)pxl1, (const float*)pxr1,
                                w1e, att1, bias1, (float*)ph1);

    dim3 g2((NN + 127) / 128, 2);   // y: 0 -> w2l, 1 -> w2r
    k_gemm<<<g2, 256, smem>>>((const float*)ph1, w2l, w2r, b2l, b2r,
                              (float*)pxl2, (float*)pxr2, NN, 64);

    k_gat2<<<gat_blocks, 256>>>((const float*)pxl2, (const float*)pxr2,
                                w2e, att2, bias2, wc, bc, out);
}